// round 11
// baseline (speedup 1.0000x reference)
#include <cuda_runtime.h>
#include <math.h>

#define BB   64
#define NCC  20
#define KK   150
#define CC   2048
#define C4   (CC/4)
#define TL   750
#define T_NCE 0.07f
#define EPSF  1e-7f

// ---------------- scratch (device globals; unique writer per slot) ----------------------
__device__ float4 g_Sp [4][2][BB*C4];   // pass1: K-chunk partial column sums of HA/HB
__device__ float4 g_SEp[8][2][BB*C4];   // pass2: K-chunk partial column sums of EB/EA
__device__ float  g_dot[2][BB*KK];      // raw S_i . e_k
__device__ float  g_nrm[2][BB*KK];      // ||e_k||^2
__device__ float  g_nce[2*BB];
__device__ float  g_cls;
__device__ float  g_rel[8][2];
__device__ float  g_actw[TL];
__device__ float  g_acts[TL];
__device__ unsigned g_ctr = 0;          // last-block counter (self-resetting each replay)

// ================= k1: stream HA,HB (157 MB) -> g_Sp; plus cls/rel/act losses =========
// blocks [0,1024): qsum  (t,n,ct,ks) ; 1024: cls ; 1025..1032: rel ; 1033..1220: act
__global__ void __launch_bounds__(256) k1(
    const float* __restrict__ HA, const float* __restrict__ HB,
    const float* __restrict__ vs, const float* __restrict__ lab,
    const float* __restrict__ rs, const float* __restrict__ rd,
    const float* __restrict__ a0, const float* __restrict__ a2)
{
    int bx = blockIdx.x, tid = threadIdx.x;
    if (bx < 1024) {
        int t = bx >> 9, rem = bx & 511;
        int n = rem >> 3, ct = (rem >> 2) & 1, ks = rem & 3;
        int k0 = (ks * KK) >> 2, k1e = ((ks + 1) * KK) >> 2;
        int c4 = ct * 256 + tid;
        const float4* src = (const float4*)(t ? HB : HA) + (size_t)(n * KK + k0) * C4 + c4;
        float4 sa = make_float4(0.f, 0.f, 0.f, 0.f);
        float4 sb = make_float4(0.f, 0.f, 0.f, 0.f);
        int k = k0;
#pragma unroll 4
        for (; k + 1 < k1e; k += 2) {
            float4 e0 = __ldcs(src);       src += C4;
            float4 e1 = __ldcs(src);       src += C4;
            sa.x += e0.x; sa.y += e0.y; sa.z += e0.z; sa.w += e0.w;
            sb.x += e1.x; sb.y += e1.y; sb.z += e1.z; sb.w += e1.w;
        }
        if (k < k1e) {
            float4 e0 = __ldcs(src);
            sa.x += e0.x; sa.y += e0.y; sa.z += e0.z; sa.w += e0.w;
        }
        sa.x += sb.x; sa.y += sb.y; sa.z += sb.z; sa.w += sb.w;
        g_Sp[ks][t][n * C4 + c4] = sa;
    } else if (bx == 1024) {
        // loss_cls
        __shared__ float rowsum[BB];
        __shared__ float sm[8];
        if (tid < BB) {
            float s = 0.f;
            for (int c = 0; c < NCC; ++c) s += lab[tid * NCC + c];
            rowsum[tid] = s;
        }
        __syncthreads();
        float acc = 0.f;
        for (int e = tid; e < BB * NCC; e += 256) {
            int n = e / NCC;
            float l = lab[e] / rowsum[n];
            float v = fminf(fmaxf(vs[e], EPSF), 1.f - EPSF);
            acc += l * logf(v) + (1.f - l) * log1pf(-v);
        }
        for (int o = 16; o; o >>= 1) acc += __shfl_down_sync(~0u, acc, o);
        if ((tid & 31) == 0) sm[tid >> 5] = acc;
        __syncthreads();
        if (tid == 0) {
            float t2 = 0.f;
            for (int w = 0; w < 8; ++w) t2 += sm[w];
            g_cls = t2;
        }
    } else if (bx <= 1032) {
        // loss_rel partials
        int blk = bx - 1025;
        __shared__ float sma[8], smb[8];
        float ss = 0.f, sd = 0.f;
        for (int e = blk * 256 + tid; e < 2 * BB * TL; e += 8 * 256) {
            float a = 1.f - rs[e]; ss += a * a;
            float b = rd[e];       sd += b * b;
        }
        for (int o = 16; o; o >>= 1) {
            ss += __shfl_down_sync(~0u, ss, o);
            sd += __shfl_down_sync(~0u, sd, o);
        }
        if ((tid & 31) == 0) { sma[tid >> 5] = ss; smb[tid >> 5] = sd; }
        __syncthreads();
        if (tid == 0) {
            float S = 0.f, D = 0.f;
            for (int w = 0; w < 8; ++w) { S += sma[w]; D += smb[w]; }
            g_rel[blk][0] = S; g_rel[blk][1] = D;
        }
    } else {
        // loss_act: 4 time-steps per block; 64 lanes = batch
        int tg = tid >> 6;            // 0..3
        int b  = tid & 63;
        int hf = (tid >> 5) & 1;      // warp-in-group
        int t  = (bx - 1033) * 4 + tg;
        bool valid = t < TL;
        float a0t = valid ? a0[b * TL + t] : 0.f;
        float a2t = valid ? a2[b * TL + t] : 0.f;
        __shared__ float smq[4][2], sma2[4][2];
        float local = 0.f;
        for (int j = 0; j < 11; ++j) {
            float sq = 0.f, ab = 0.f;
            if (valid) {
                int c = t + j - 6; c = c < 0 ? 0 : (c > TL - 1 ? TL - 1 : c);
                float d0 = a0t - a0[b * TL + c]; sq = d0 * d0;
                ab = fabsf(a2t - a2[b * TL + c]);
            }
            for (int o = 16; o; o >>= 1) {
                sq += __shfl_down_sync(~0u, sq, o);
                ab += __shfl_down_sync(~0u, ab, o);
            }
            if ((tid & 31) == 0) { smq[tg][hf] = sq; sma2[tg][hf] = ab; }
            __syncthreads();
            if ((tid & 63) == 0) {
                float SQ = smq[tg][0] + smq[tg][1];
                float AB = sma2[tg][0] + sma2[tg][1];
                local += expf(-0.5f * SQ) * (AB * (1.f / BB));
            }
            __syncthreads();
        }
        if ((tid & 63) == 0 && valid) g_actw[t] = local;
        float d = valid ? (a0t - a2t) * (a0t - a2t) : 0.f;
        for (int o = 16; o; o >>= 1) d += __shfl_down_sync(~0u, d, o);
        if ((tid & 31) == 0) smq[tg][hf] = d;
        __syncthreads();
        if ((tid & 63) == 0 && valid) g_acts[t] = smq[tg][0] + smq[tg][1];
    }
}

// ================= k2: stream EA,EB (157 MB) -> raw dots, norms, SE partials ==========
// 1024 blocks = (i, n, ks). Per-thread partials go to smem; NO cross-lane ops in loop.
// Depth-2 prefetch keeps 4 float4 loads in flight per thread.
__global__ void __launch_bounds__(256) k2(const float* __restrict__ EA,
                                          const float* __restrict__ EB)
{
    __shared__ float sdp[19][256];
    __shared__ float snp[19][256];

    int bx = blockIdx.x, tid = threadIdx.x;
    int i = bx >> 9, rem = bx & 511;
    int n = rem >> 3, ks = rem & 7;
    int k0 = (ks * KK) >> 3, k1e = ((ks + 1) * KK) >> 3;
    int cnt = k1e - k0;                      // 18 or 19 (always >= 2)
    int wid = tid >> 5, lane = tid & 31;

    // q = raw S_i[n] (sum of 4 K-chunk partials)
    float4 q0 = make_float4(0.f, 0.f, 0.f, 0.f), q1 = q0;
#pragma unroll
    for (int p = 0; p < 4; ++p) {
        float4 a = g_Sp[p][i][n * C4 + tid];
        float4 b = g_Sp[p][i][n * C4 + 256 + tid];
        q0.x += a.x; q0.y += a.y; q0.z += a.z; q0.w += a.w;
        q1.x += b.x; q1.y += b.y; q1.z += b.z; q1.w += b.w;
    }

    const float4* src = (const float4*)(i ? EA : EB) + (size_t)(n * KK + k0) * C4;
    float4 s0 = make_float4(0.f, 0.f, 0.f, 0.f), s1 = s0;

    // depth-2 software pipeline
    float4 e0a = __ldcs(src + tid);
    float4 e1a = __ldcs(src + 256 + tid);
    src += C4;
    float4 e0b = __ldcs(src + tid);
    float4 e1b = __ldcs(src + 256 + tid);
    src += C4;

    for (int k = 0; k < cnt; ++k) {
        float4 f0 = make_float4(0.f, 0.f, 0.f, 0.f), f1 = f0;
        if (k + 2 < cnt) {
            f0 = __ldcs(src + tid);
            f1 = __ldcs(src + 256 + tid);
            src += C4;
        }
        s0.x += e0a.x; s0.y += e0a.y; s0.z += e0a.z; s0.w += e0a.w;
        s1.x += e1a.x; s1.y += e1a.y; s1.z += e1a.z; s1.w += e1a.w;
        float d  = q0.x*e0a.x + q0.y*e0a.y + q0.z*e0a.z + q0.w*e0a.w
                 + q1.x*e1a.x + q1.y*e1a.y + q1.z*e1a.z + q1.w*e1a.w;
        float nn = e0a.x*e0a.x + e0a.y*e0a.y + e0a.z*e0a.z + e0a.w*e0a.w
                 + e1a.x*e1a.x + e1a.y*e1a.y + e1a.z*e1a.z + e1a.w*e1a.w;
        sdp[k][tid] = d;                    // per-thread partial; no cross-lane dependency
        snp[k][tid] = nn;
        e0a = e0b; e1a = e1b; e0b = f0; e1b = f1;
    }

    g_SEp[ks][i][n * C4 + tid] = s0;
    g_SEp[ks][i][n * C4 + 256 + tid] = s1;

    __syncthreads();
    // deferred reductions: 2*cnt arrays of 256 values, one per warp-round
    for (int r = wid; r < 2 * cnt; r += 8) {
        int k = r >> 1;
        const float* a = (r & 1) ? &snp[k][0] : &sdp[k][0];
        float v = 0.f;
#pragma unroll
        for (int j = 0; j < 8; ++j) v += a[lane + 32 * j];
        for (int o = 16; o; o >>= 1) v += __shfl_down_sync(~0u, v, o);
        if (lane == 0) {
            if (r & 1) g_nrm[i][n * KK + k0 + k] = v;
            else       g_dot[i][n * KK + k0 + k] = v;
        }
    }
}

// ================= k3: per-(i,n) NCE loss; last block combines everything ============
__global__ void __launch_bounds__(256) k3(const float* __restrict__ att,
                                          float* __restrict__ out)
{
    int i = blockIdx.x >> 6, n = blockIdx.x & 63;
    int tid = threadIdx.x, wid = tid >> 5, lane = tid & 31;

    float4 S0 = make_float4(0.f,0.f,0.f,0.f), S1 = S0, E0 = S0, E1 = S0;
#pragma unroll
    for (int p = 0; p < 4; ++p) {
        float4 a = g_Sp[p][i][n * C4 + tid];
        float4 b = g_Sp[p][i][n * C4 + 256 + tid];
        S0.x += a.x; S0.y += a.y; S0.z += a.z; S0.w += a.w;
        S1.x += b.x; S1.y += b.y; S1.z += b.z; S1.w += b.w;
    }
#pragma unroll
    for (int p = 0; p < 8; ++p) {
        float4 a = g_SEp[p][1 - i][n * C4 + tid];
        float4 b = g_SEp[p][1 - i][n * C4 + 256 + tid];
        E0.x += a.x; E0.y += a.y; E0.z += a.z; E0.w += a.w;
        E1.x += b.x; E1.y += b.y; E1.z += b.z; E1.w += b.w;
    }
    float qss  = S0.x*S0.x+S0.y*S0.y+S0.z*S0.z+S0.w*S0.w + S1.x*S1.x+S1.y*S1.y+S1.z*S1.z+S1.w*S1.w;
    float sess = E0.x*E0.x+E0.y*E0.y+E0.z*E0.z+E0.w*E0.w + E1.x*E1.x+E1.y*E1.y+E1.z*E1.z+E1.w*E1.w;
    float dse  = S0.x*E0.x+S0.y*E0.y+S0.z*E0.z+S0.w*E0.w + S1.x*E1.x+S1.y*E1.y+S1.z*E1.z+S1.w*E1.w;

    __shared__ float sm[8][4];
    __shared__ float bc[2];
    for (int o = 16; o; o >>= 1) {
        qss  += __shfl_down_sync(~0u, qss,  o);
        sess += __shfl_down_sync(~0u, sess, o);
        dse  += __shfl_down_sync(~0u, dse,  o);
    }
    if (lane == 0) { sm[wid][0] = qss; sm[wid][1] = sess; sm[wid][2] = dse; }
    __syncthreads();
    if (tid == 0) {
        float Q = 0.f, S = 0.f, D = 0.f;
        for (int w = 0; w < 8; ++w) { Q += sm[w][0]; S += sm[w][1]; D += sm[w][2]; }
        float rq = rsqrtf(Q);
        bc[0] = rq;
        bc[1] = D * rq * rsqrtf(S) * (1.f / T_NCE);    // logit0
    }
    __syncthreads();
    float rq = bc[0], logit0 = bc[1];

    float logit = -1e30f;
    if (tid == 0) logit = logit0;
    else if (tid <= 150) {
        int k = tid - 1;
        logit = att[n * 300 + i * 150 + k] * g_dot[i][n * KK + k] * rq
              * rsqrtf(g_nrm[i][n * KK + k]) * (1.f / T_NCE);
    }
    // block max
    float mx = logit;
    for (int o = 16; o; o >>= 1) mx = fmaxf(mx, __shfl_xor_sync(~0u, mx, o));
    if (lane == 0) sm[wid][0] = mx;
    __syncthreads();
    if (tid == 0) {
        float M = -1e30f;
        for (int w = 0; w < 8; ++w) M = fmaxf(M, sm[w][0]);
        bc[0] = M;
    }
    __syncthreads();
    float M = bc[0];
    float ex = (tid <= 150) ? expf(logit - M) : 0.f;
    for (int o = 16; o; o >>= 1) ex += __shfl_down_sync(~0u, ex, o);
    if (lane == 0) sm[wid][1] = ex;
    __syncthreads();
    if (tid == 0) {
        float SE = 0.f;
        for (int w = 0; w < 8; ++w) SE += sm[w][1];
        g_nce[i * 64 + n] = logf(SE) + M - logit0;     // -log_softmax[0]
    }

    // ---- last-block final combine ----
    __shared__ unsigned last;
    __threadfence();
    __syncthreads();
    if (tid == 0) last = (atomicAdd(&g_ctr, 1u) == (unsigned)(gridDim.x - 1)) ? 1u : 0u;
    __syncthreads();
    if (!last) return;
    __threadfence();   // acquire: see all blocks' g_nce writes

    float sn2 = 0.f, sw = 0.f, ss = 0.f, sr = 0.f;
    for (int e = tid; e < 2 * BB; e += 256) sn2 += g_nce[e];
    for (int e = tid; e < TL; e += 256) { sw += g_actw[e]; ss += g_acts[e]; }
    if (tid < 16) sr = g_rel[tid >> 1][tid & 1];
    for (int o = 16; o; o >>= 1) {
        sn2 += __shfl_down_sync(~0u, sn2, o);
        sw  += __shfl_down_sync(~0u, sw,  o);
        ss  += __shfl_down_sync(~0u, ss,  o);
        sr  += __shfl_down_sync(~0u, sr,  o);
    }
    if (lane == 0) { sm[wid][0]=sn2; sm[wid][1]=sw; sm[wid][2]=ss; sm[wid][3]=sr; }
    __syncthreads();
    if (tid == 0) {
        float SN=0.f, SW=0.f, SS=0.f, SR=0.f;
        for (int w = 0; w < 8; ++w) { SN+=sm[w][0]; SW+=sm[w][1]; SS+=sm[w][2]; SR+=sm[w][3]; }
        float cls   = -g_cls * (1.f / (BB * NCC));
        float rel   = SR * (1.f / (2 * BB * TL));
        float act   = SW + 0.1f * SS * (1.f / BB);     // E_THETA=0.1, E_ALPHA=1
        float snico = SN * (1.f / BB);
        out[0] = cls + 0.01f * snico + act + 0.1f * rel;
        out[1] = cls; out[2] = snico; out[3] = act; out[4] = rel;
        g_ctr = 0;                                     // reset for next graph replay
    }
}

extern "C" void kernel_launch(void* const* d_in, const int* in_sizes, int n_in,
                              void* d_out, int out_size) {
    const float* video = (const float*)d_in[0];
    const float* label = (const float*)d_in[1];
    const float* HA    = (const float*)d_in[2];
    const float* EA    = (const float*)d_in[3];
    const float* HB    = (const float*)d_in[4];
    const float* EB    = (const float*)d_in[5];
    const float* rs    = (const float*)d_in[6];
    const float* rd    = (const float*)d_in[7];
    const float* a0    = (const float*)d_in[8];
    const float* a2    = (const float*)d_in[9];
    const float* att   = (const float*)d_in[10];
    float* out = (float*)d_out;

    k1<<<1033 + 188, 256>>>(HA, HB, video, label, rs, rd, a0, a2);
    k2<<<1024, 256>>>(EA, EB);
    k3<<<128, 256>>>(att, out);
    (void)in_sizes; (void)n_in; (void)out_size;
}

// round 12
// speedup vs baseline: 1.0005x; 1.0005x over previous
#include <cuda_runtime.h>
#include <math.h>

#define BB   64
#define NCC  20
#define KK   150
#define CC   2048
#define C4   (CC/4)
#define TL   750
#define T_NCE 0.07f
#define EPSF  1e-7f

// ---------------- scratch (device globals; unique writer per slot) ----------------------
__device__ float4 g_Sp [4][2][BB*C4];   // pass1: K-chunk partial column sums of HA/HB
__device__ float4 g_SEp[8][2][BB*C4];   // pass2: K-chunk partial column sums of EB/EA
__device__ float  g_dotp[2][2][BB*KK];  // [half][i] raw S_i . e_k (half-row partials)
__device__ float  g_nrmp[2][2][BB*KK];  // [half][i] ||e_k||^2 (half-row partials)
__device__ float  g_nce[2*BB];
__device__ float  g_cls;
__device__ float  g_rel[8][2];
__device__ float  g_actw[TL];
__device__ float  g_acts[TL];
__device__ unsigned g_ctr = 0;          // last-block counter (self-resetting each replay)

// ================= k1: stream HA,HB (157 MB) -> g_Sp; plus cls/rel/act losses =========
// blocks [0,1024): qsum  (t,n,ct,ks) ; 1024: cls ; 1025..1032: rel ; 1033..1220: act
__global__ void __launch_bounds__(256) k1(
    const float* __restrict__ HA, const float* __restrict__ HB,
    const float* __restrict__ vs, const float* __restrict__ lab,
    const float* __restrict__ rs, const float* __restrict__ rd,
    const float* __restrict__ a0, const float* __restrict__ a2)
{
    int bx = blockIdx.x, tid = threadIdx.x;
    if (bx < 1024) {
        int t = bx >> 9, rem = bx & 511;
        int n = rem >> 3, ct = (rem >> 2) & 1, ks = rem & 3;
        int k0 = (ks * KK) >> 2, k1e = ((ks + 1) * KK) >> 2;
        int c4 = ct * 256 + tid;
        const float4* src = (const float4*)(t ? HB : HA) + (size_t)(n * KK + k0) * C4 + c4;
        float4 sa = make_float4(0.f, 0.f, 0.f, 0.f);
        float4 sb = make_float4(0.f, 0.f, 0.f, 0.f);
        int k = k0;
#pragma unroll 4
        for (; k + 1 < k1e; k += 2) {
            float4 e0 = __ldcs(src);       src += C4;
            float4 e1 = __ldcs(src);       src += C4;
            sa.x += e0.x; sa.y += e0.y; sa.z += e0.z; sa.w += e0.w;
            sb.x += e1.x; sb.y += e1.y; sb.z += e1.z; sb.w += e1.w;
        }
        if (k < k1e) {
            float4 e0 = __ldcs(src);
            sa.x += e0.x; sa.y += e0.y; sa.z += e0.z; sa.w += e0.w;
        }
        sa.x += sb.x; sa.y += sb.y; sa.z += sb.z; sa.w += sb.w;
        g_Sp[ks][t][n * C4 + c4] = sa;
    } else if (bx == 1024) {
        // loss_cls
        __shared__ float rowsum[BB];
        __shared__ float sm[8];
        if (tid < BB) {
            float s = 0.f;
            for (int c = 0; c < NCC; ++c) s += lab[tid * NCC + c];
            rowsum[tid] = s;
        }
        __syncthreads();
        float acc = 0.f;
        for (int e = tid; e < BB * NCC; e += 256) {
            int n = e / NCC;
            float l = lab[e] / rowsum[n];
            float v = fminf(fmaxf(vs[e], EPSF), 1.f - EPSF);
            acc += l * logf(v) + (1.f - l) * log1pf(-v);
        }
        for (int o = 16; o; o >>= 1) acc += __shfl_down_sync(~0u, acc, o);
        if ((tid & 31) == 0) sm[tid >> 5] = acc;
        __syncthreads();
        if (tid == 0) {
            float t2 = 0.f;
            for (int w = 0; w < 8; ++w) t2 += sm[w];
            g_cls = t2;
        }
    } else if (bx <= 1032) {
        // loss_rel partials
        int blk = bx - 1025;
        __shared__ float sma[8], smb[8];
        float ss = 0.f, sd = 0.f;
        for (int e = blk * 256 + tid; e < 2 * BB * TL; e += 8 * 256) {
            float a = 1.f - rs[e]; ss += a * a;
            float b = rd[e];       sd += b * b;
        }
        for (int o = 16; o; o >>= 1) {
            ss += __shfl_down_sync(~0u, ss, o);
            sd += __shfl_down_sync(~0u, sd, o);
        }
        if ((tid & 31) == 0) { sma[tid >> 5] = ss; smb[tid >> 5] = sd; }
        __syncthreads();
        if (tid == 0) {
            float S = 0.f, D = 0.f;
            for (int w = 0; w < 8; ++w) { S += sma[w]; D += smb[w]; }
            g_rel[blk][0] = S; g_rel[blk][1] = D;
        }
    } else {
        // loss_act: 4 time-steps per block; 64 lanes = batch
        int tg = tid >> 6;            // 0..3
        int b  = tid & 63;
        int hf = (tid >> 5) & 1;      // warp-in-group
        int t  = (bx - 1033) * 4 + tg;
        bool valid = t < TL;
        float a0t = valid ? a0[b * TL + t] : 0.f;
        float a2t = valid ? a2[b * TL + t] : 0.f;
        __shared__ float smq[4][2], sma2[4][2];
        float local = 0.f;
        for (int j = 0; j < 11; ++j) {
            float sq = 0.f, ab = 0.f;
            if (valid) {
                int c = t + j - 6; c = c < 0 ? 0 : (c > TL - 1 ? TL - 1 : c);
                float d0 = a0t - a0[b * TL + c]; sq = d0 * d0;
                ab = fabsf(a2t - a2[b * TL + c]);
            }
            for (int o = 16; o; o >>= 1) {
                sq += __shfl_down_sync(~0u, sq, o);
                ab += __shfl_down_sync(~0u, ab, o);
            }
            if ((tid & 31) == 0) { smq[tg][hf] = sq; sma2[tg][hf] = ab; }
            __syncthreads();
            if ((tid & 63) == 0) {
                float SQ = smq[tg][0] + smq[tg][1];
                float AB = sma2[tg][0] + sma2[tg][1];
                local += expf(-0.5f * SQ) * (AB * (1.f / BB));
            }
            __syncthreads();
        }
        if ((tid & 63) == 0 && valid) g_actw[t] = local;
        float d = valid ? (a0t - a2t) * (a0t - a2t) : 0.f;
        for (int o = 16; o; o >>= 1) d += __shfl_down_sync(~0u, d, o);
        if ((tid & 31) == 0) smq[tg][hf] = d;
        __syncthreads();
        if ((tid & 63) == 0 && valid) g_acts[t] = smq[tg][0] + smq[tg][1];
    }
}

// ================= k2: stream EA,EB (157 MB) -> half-row dots, norms, SE partials =====
// 2048 blocks = (i, n, ks, h). Block owns a half-row (256 float4); 1 float4/thread.
// In-loop: pair-shuffle only (depth-1); per-pair partials to smem; reductions deferred.
__global__ void __launch_bounds__(256, 6) k2(const float* __restrict__ EA,
                                             const float* __restrict__ EB)
{
    __shared__ float sdp[19][128];
    __shared__ float snp[19][128];

    int bx = blockIdx.x, tid = threadIdx.x;
    int i = bx >> 10, rem = bx & 1023;
    int n = rem >> 4, ks = (rem >> 1) & 7, h = rem & 1;
    int k0 = (ks * KK) >> 3, k1e = ((ks + 1) * KK) >> 3;
    int cnt = k1e - k0;                      // 18 or 19
    int wid = tid >> 5, lane = tid & 31;
    int col = h * 256 + tid;                 // float4 column index in [0,512)

    // q = raw S_i[n] at this thread's column (sum of 4 K-chunk partials)
    float4 q = make_float4(0.f, 0.f, 0.f, 0.f);
#pragma unroll
    for (int p = 0; p < 4; ++p) {
        float4 a = g_Sp[p][i][n * C4 + col];
        q.x += a.x; q.y += a.y; q.z += a.z; q.w += a.w;
    }

    const float4* src = (const float4*)(i ? EA : EB) + (size_t)(n * KK + k0) * C4 + col;
    float4 s = make_float4(0.f, 0.f, 0.f, 0.f);

    // depth-2 software pipeline
    float4 ea = __ldcs(src); src += C4;
    float4 eb = __ldcs(src); src += C4;

    for (int k = 0; k < cnt; ++k) {
        float4 f = make_float4(0.f, 0.f, 0.f, 0.f);
        if (k + 2 < cnt) { f = __ldcs(src); src += C4; }
        s.x += ea.x; s.y += ea.y; s.z += ea.z; s.w += ea.w;
        float d  = q.x*ea.x + q.y*ea.y + q.z*ea.z + q.w*ea.w;
        float nn = ea.x*ea.x + ea.y*ea.y + ea.z*ea.z + ea.w*ea.w;
        d  += __shfl_down_sync(~0u, d,  1);          // depth-1 pair reduce
        nn += __shfl_down_sync(~0u, nn, 1);
        if (!(lane & 1)) { sdp[k][tid >> 1] = d; snp[k][tid >> 1] = nn; }
        ea = eb; eb = f;
    }

    g_SEp[ks][i][n * C4 + col] = s;

    __syncthreads();
    // deferred reductions: 2*cnt arrays of 128 values, one per warp-round
    for (int r = wid; r < 2 * cnt; r += 8) {
        int k = r >> 1;
        const float* a = (r & 1) ? &snp[k][0] : &sdp[k][0];
        float v = a[lane] + a[lane + 32] + a[lane + 64] + a[lane + 96];
        for (int o = 16; o; o >>= 1) v += __shfl_down_sync(~0u, v, o);
        if (lane == 0) {
            if (r & 1) g_nrmp[h][i][n * KK + k0 + k] = v;
            else       g_dotp[h][i][n * KK + k0 + k] = v;
        }
    }
}

// ================= k3: per-(i,n) NCE loss; last block combines everything ============
__global__ void __launch_bounds__(256) k3(const float* __restrict__ att,
                                          float* __restrict__ out)
{
    int i = blockIdx.x >> 6, n = blockIdx.x & 63;
    int tid = threadIdx.x, wid = tid >> 5, lane = tid & 31;

    float4 S0 = make_float4(0.f,0.f,0.f,0.f), S1 = S0, E0 = S0, E1 = S0;
#pragma unroll
    for (int p = 0; p < 4; ++p) {
        float4 a = g_Sp[p][i][n * C4 + tid];
        float4 b = g_Sp[p][i][n * C4 + 256 + tid];
        S0.x += a.x; S0.y += a.y; S0.z += a.z; S0.w += a.w;
        S1.x += b.x; S1.y += b.y; S1.z += b.z; S1.w += b.w;
    }
#pragma unroll
    for (int p = 0; p < 8; ++p) {
        float4 a = g_SEp[p][1 - i][n * C4 + tid];
        float4 b = g_SEp[p][1 - i][n * C4 + 256 + tid];
        E0.x += a.x; E0.y += a.y; E0.z += a.z; E0.w += a.w;
        E1.x += b.x; E1.y += b.y; E1.z += b.z; E1.w += b.w;
    }
    float qss  = S0.x*S0.x+S0.y*S0.y+S0.z*S0.z+S0.w*S0.w + S1.x*S1.x+S1.y*S1.y+S1.z*S1.z+S1.w*S1.w;
    float sess = E0.x*E0.x+E0.y*E0.y+E0.z*E0.z+E0.w*E0.w + E1.x*E1.x+E1.y*E1.y+E1.z*E1.z+E1.w*E1.w;
    float dse  = S0.x*E0.x+S0.y*E0.y+S0.z*E0.z+S0.w*E0.w + S1.x*E1.x+S1.y*E1.y+S1.z*E1.z+S1.w*E1.w;

    __shared__ float sm[8][4];
    __shared__ float bc[2];
    for (int o = 16; o; o >>= 1) {
        qss  += __shfl_down_sync(~0u, qss,  o);
        sess += __shfl_down_sync(~0u, sess, o);
        dse  += __shfl_down_sync(~0u, dse,  o);
    }
    if (lane == 0) { sm[wid][0] = qss; sm[wid][1] = sess; sm[wid][2] = dse; }
    __syncthreads();
    if (tid == 0) {
        float Q = 0.f, S = 0.f, D = 0.f;
        for (int w = 0; w < 8; ++w) { Q += sm[w][0]; S += sm[w][1]; D += sm[w][2]; }
        float rq = rsqrtf(Q);
        bc[0] = rq;
        bc[1] = D * rq * rsqrtf(S) * (1.f / T_NCE);    // logit0
    }
    __syncthreads();
    float rq = bc[0], logit0 = bc[1];

    float logit = -1e30f;
    if (tid == 0) logit = logit0;
    else if (tid <= 150) {
        int k = tid - 1;
        float dd = g_dotp[0][i][n * KK + k] + g_dotp[1][i][n * KK + k];
        float nn = g_nrmp[0][i][n * KK + k] + g_nrmp[1][i][n * KK + k];
        logit = att[n * 300 + i * 150 + k] * dd * rq * rsqrtf(nn) * (1.f / T_NCE);
    }
    // block max
    float mx = logit;
    for (int o = 16; o; o >>= 1) mx = fmaxf(mx, __shfl_xor_sync(~0u, mx, o));
    if (lane == 0) sm[wid][0] = mx;
    __syncthreads();
    if (tid == 0) {
        float M = -1e30f;
        for (int w = 0; w < 8; ++w) M = fmaxf(M, sm[w][0]);
        bc[0] = M;
    }
    __syncthreads();
    float M = bc[0];
    float ex = (tid <= 150) ? expf(logit - M) : 0.f;
    for (int o = 16; o; o >>= 1) ex += __shfl_down_sync(~0u, ex, o);
    if (lane == 0) sm[wid][1] = ex;
    __syncthreads();
    if (tid == 0) {
        float SE = 0.f;
        for (int w = 0; w < 8; ++w) SE += sm[w][1];
        g_nce[i * 64 + n] = logf(SE) + M - logit0;     // -log_softmax[0]
    }

    // ---- last-block final combine ----
    __shared__ unsigned last;
    __threadfence();
    __syncthreads();
    if (tid == 0) last = (atomicAdd(&g_ctr, 1u) == (unsigned)(gridDim.x - 1)) ? 1u : 0u;
    __syncthreads();
    if (!last) return;
    __threadfence();   // acquire: see all blocks' g_nce writes

    float sn2 = 0.f, sw = 0.f, ss = 0.f, sr = 0.f;
    for (int e = tid; e < 2 * BB; e += 256) sn2 += g_nce[e];
    for (int e = tid; e < TL; e += 256) { sw += g_actw[e]; ss += g_acts[e]; }
    if (tid < 16) sr = g_rel[tid >> 1][tid & 1];
    for (int o = 16; o; o >>= 1) {
        sn2 += __shfl_down_sync(~0u, sn2, o);
        sw  += __shfl_down_sync(~0u, sw,  o);
        ss  += __shfl_down_sync(~0u, ss,  o);
        sr  += __shfl_down_sync(~0u, sr,  o);
    }
    if (lane == 0) { sm[wid][0]=sn2; sm[wid][1]=sw; sm[wid][2]=ss; sm[wid][3]=sr; }
    __syncthreads();
    if (tid == 0) {
        float SN=0.f, SW=0.f, SS=0.f, SR=0.f;
        for (int w = 0; w < 8; ++w) { SN+=sm[w][0]; SW+=sm[w][1]; SS+=sm[w][2]; SR+=sm[w][3]; }
        float cls   = -g_cls * (1.f / (BB * NCC));
        float rel   = SR * (1.f / (2 * BB * TL));
        float act   = SW + 0.1f * SS * (1.f / BB);     // E_THETA=0.1, E_ALPHA=1
        float snico = SN * (1.f / BB);
        out[0] = cls + 0.01f * snico + act + 0.1f * rel;
        out[1] = cls; out[2] = snico; out[3] = act; out[4] = rel;
        g_ctr = 0;                                     // reset for next graph replay
    }
}

extern "C" void kernel_launch(void* const* d_in, const int* in_sizes, int n_in,
                              void* d_out, int out_size) {
    const float* video = (const float*)d_in[0];
    const float* label = (const float*)d_in[1];
    const float* HA    = (const float*)d_in[2];
    const float* EA    = (const float*)d_in[3];
    const float* HB    = (const float*)d_in[4];
    const float* EB    = (const float*)d_in[5];
    const float* rs    = (const float*)d_in[6];
    const float* rd    = (const float*)d_in[7];
    const float* a0    = (const float*)d_in[8];
    const float* a2    = (const float*)d_in[9];
    const float* att   = (const float*)d_in[10];
    float* out = (float*)d_out;

    k1<<<1033 + 188, 256>>>(HA, HB, video, label, rs, rd, a0, a2);
    k2<<<2048, 256>>>(EA, EB);
    k3<<<128, 256>>>(att, out);
    (void)in_sizes; (void)n_in; (void)out_size;
}

// round 13
// speedup vs baseline: 1.0367x; 1.0362x over previous
#include <cuda_runtime.h>
#include <math.h>

#define BB   64
#define NCC  20
#define KK   150
#define CC   2048
#define C4   (CC/4)
#define TL   750
#define T_NCE 0.07f
#define EPSF  1e-7f

// ---------------- scratch (device globals; unique writer per slot) ----------------------
__device__ float4 g_Sp [4][2][BB*C4];    // pass1: K-chunk partial column sums of HA/HB
__device__ float4 g_SEp[10][2][BB*C4];   // pass2: K-chunk partial column sums of EB/EA
__device__ float  g_dotp[2][2][BB*KK];   // [half][i] raw S_i . e_k (half-row partials)
__device__ float  g_nrmp[2][2][BB*KK];   // [half][i] ||e_k||^2 (half-row partials)
__device__ float  g_nce[2*BB];
__device__ float  g_cls;
__device__ float  g_rel[8][2];
__device__ float  g_actw[TL];
__device__ float  g_acts[TL];
__device__ unsigned g_ctr = 0;           // last-block counter (self-resetting each replay)

// ================= k1: stream HA,HB (157 MB) -> g_Sp; plus cls/rel/act losses =========
// blocks [0,1024): qsum  (t,n,ct,ks) ; 1024: cls ; 1025..1032: rel ; 1033..1220: act
__global__ void __launch_bounds__(256) k1(
    const float* __restrict__ HA, const float* __restrict__ HB,
    const float* __restrict__ vs, const float* __restrict__ lab,
    const float* __restrict__ rs, const float* __restrict__ rd,
    const float* __restrict__ a0, const float* __restrict__ a2)
{
    int bx = blockIdx.x, tid = threadIdx.x;
    if (bx < 1024) {
        int t = bx >> 9, rem = bx & 511;
        int n = rem >> 3, ct = (rem >> 2) & 1, ks = rem & 3;
        int k0 = (ks * KK) >> 2, k1e = ((ks + 1) * KK) >> 2;
        int c4 = ct * 256 + tid;
        const float4* src = (const float4*)(t ? HB : HA) + (size_t)(n * KK + k0) * C4 + c4;
        float4 sa = make_float4(0.f, 0.f, 0.f, 0.f);
        float4 sb = make_float4(0.f, 0.f, 0.f, 0.f);
        int k = k0;
#pragma unroll 4
        for (; k + 1 < k1e; k += 2) {
            float4 e0 = __ldcs(src);       src += C4;
            float4 e1 = __ldcs(src);       src += C4;
            sa.x += e0.x; sa.y += e0.y; sa.z += e0.z; sa.w += e0.w;
            sb.x += e1.x; sb.y += e1.y; sb.z += e1.z; sb.w += e1.w;
        }
        if (k < k1e) {
            float4 e0 = __ldcs(src);
            sa.x += e0.x; sa.y += e0.y; sa.z += e0.z; sa.w += e0.w;
        }
        sa.x += sb.x; sa.y += sb.y; sa.z += sb.z; sa.w += sb.w;
        g_Sp[ks][t][n * C4 + c4] = sa;
    } else if (bx == 1024) {
        // loss_cls
        __shared__ float rowsum[BB];
        __shared__ float sm[8];
        if (tid < BB) {
            float s = 0.f;
            for (int c = 0; c < NCC; ++c) s += lab[tid * NCC + c];
            rowsum[tid] = s;
        }
        __syncthreads();
        float acc = 0.f;
        for (int e = tid; e < BB * NCC; e += 256) {
            int n = e / NCC;
            float l = lab[e] / rowsum[n];
            float v = fminf(fmaxf(vs[e], EPSF), 1.f - EPSF);
            acc += l * logf(v) + (1.f - l) * log1pf(-v);
        }
        for (int o = 16; o; o >>= 1) acc += __shfl_down_sync(~0u, acc, o);
        if ((tid & 31) == 0) sm[tid >> 5] = acc;
        __syncthreads();
        if (tid == 0) {
            float t2 = 0.f;
            for (int w = 0; w < 8; ++w) t2 += sm[w];
            g_cls = t2;
        }
    } else if (bx <= 1032) {
        // loss_rel partials
        int blk = bx - 1025;
        __shared__ float sma[8], smb[8];
        float ss = 0.f, sd = 0.f;
        for (int e = blk * 256 + tid; e < 2 * BB * TL; e += 8 * 256) {
            float a = 1.f - rs[e]; ss += a * a;
            float b = rd[e];       sd += b * b;
        }
        for (int o = 16; o; o >>= 1) {
            ss += __shfl_down_sync(~0u, ss, o);
            sd += __shfl_down_sync(~0u, sd, o);
        }
        if ((tid & 31) == 0) { sma[tid >> 5] = ss; smb[tid >> 5] = sd; }
        __syncthreads();
        if (tid == 0) {
            float S = 0.f, D = 0.f;
            for (int w = 0; w < 8; ++w) { S += sma[w]; D += smb[w]; }
            g_rel[blk][0] = S; g_rel[blk][1] = D;
        }
    } else {
        // loss_act: 4 time-steps per block; 64 lanes = batch
        int tg = tid >> 6;            // 0..3
        int b  = tid & 63;
        int hf = (tid >> 5) & 1;      // warp-in-group
        int t  = (bx - 1033) * 4 + tg;
        bool valid = t < TL;
        float a0t = valid ? a0[b * TL + t] : 0.f;
        float a2t = valid ? a2[b * TL + t] : 0.f;
        __shared__ float smq[4][2], sma2[4][2];
        float local = 0.f;
        for (int j = 0; j < 11; ++j) {
            float sq = 0.f, ab = 0.f;
            if (valid) {
                int c = t + j - 6; c = c < 0 ? 0 : (c > TL - 1 ? TL - 1 : c);
                float d0 = a0t - a0[b * TL + c]; sq = d0 * d0;
                ab = fabsf(a2t - a2[b * TL + c]);
            }
            for (int o = 16; o; o >>= 1) {
                sq += __shfl_down_sync(~0u, sq, o);
                ab += __shfl_down_sync(~0u, ab, o);
            }
            if ((tid & 31) == 0) { smq[tg][hf] = sq; sma2[tg][hf] = ab; }
            __syncthreads();
            if ((tid & 63) == 0) {
                float SQ = smq[tg][0] + smq[tg][1];
                float AB = sma2[tg][0] + sma2[tg][1];
                local += expf(-0.5f * SQ) * (AB * (1.f / BB));
            }
            __syncthreads();
        }
        if ((tid & 63) == 0 && valid) g_actw[t] = local;
        float d = valid ? (a0t - a2t) * (a0t - a2t) : 0.f;
        for (int o = 16; o; o >>= 1) d += __shfl_down_sync(~0u, d, o);
        if ((tid & 31) == 0) smq[tg][hf] = d;
        __syncthreads();
        if ((tid & 63) == 0 && valid) g_acts[t] = smq[tg][0] + smq[tg][1];
    }
}

// ================= k2: stream EA,EB (157 MB) -> half-row dots, norms, SE partials =====
// 2560 blocks = (i, n, ks in [0,10), h). Block owns half-row x 15 rows; COMPILE-TIME
// trip count, fully unrolled in 3 groups of 5 batched LDGs (MLP=5 per thread).
__global__ void __launch_bounds__(256, 5) k2(const float* __restrict__ EA,
                                             const float* __restrict__ EB)
{
    __shared__ float sdp[15][128];
    __shared__ float snp[15][128];

    int bx = blockIdx.x, tid = threadIdx.x;
    int h  = bx & 1;
    int t1 = bx >> 1;            // 0..1279
    int ks = t1 % 10;
    int t2 = t1 / 10;            // 0..127
    int n  = t2 & 63, i = t2 >> 6;
    int k0 = ks * 15;
    int wid = tid >> 5, lane = tid & 31;
    int col = h * 256 + tid;     // float4 column index in [0,512)

    // q = raw S_i[n] at this thread's column (sum of 4 K-chunk partials)
    float4 q = make_float4(0.f, 0.f, 0.f, 0.f);
#pragma unroll
    for (int p = 0; p < 4; ++p) {
        float4 a = g_Sp[p][i][n * C4 + col];
        q.x += a.x; q.y += a.y; q.z += a.z; q.w += a.w;
    }

    const float4* src = (const float4*)(i ? EA : EB) + (size_t)(n * KK + k0) * C4 + col;
    float4 s = make_float4(0.f, 0.f, 0.f, 0.f);

#pragma unroll
    for (int g = 0; g < 3; ++g) {
        float4 e[5];
#pragma unroll
        for (int j = 0; j < 5; ++j)            // 5 independent LDGs, front-batched
            e[j] = __ldcs(src + (size_t)(g * 5 + j) * C4);
#pragma unroll
        for (int j = 0; j < 5; ++j) {
            int k = g * 5 + j;
            s.x += e[j].x; s.y += e[j].y; s.z += e[j].z; s.w += e[j].w;
            float d  = q.x*e[j].x + q.y*e[j].y + q.z*e[j].z + q.w*e[j].w;
            float nn = e[j].x*e[j].x + e[j].y*e[j].y + e[j].z*e[j].z + e[j].w*e[j].w;
            d  += __shfl_down_sync(~0u, d,  1);          // depth-1 pair reduce
            nn += __shfl_down_sync(~0u, nn, 1);
            if (!(lane & 1)) { sdp[k][tid >> 1] = d; snp[k][tid >> 1] = nn; }
        }
    }

    g_SEp[ks][i][n * C4 + col] = s;

    __syncthreads();
    // deferred reductions: 30 arrays of 128 values, one per warp-round
    for (int r = wid; r < 30; r += 8) {
        int k = r >> 1;
        const float* a = (r & 1) ? &snp[k][0] : &sdp[k][0];
        float v = a[lane] + a[lane + 32] + a[lane + 64] + a[lane + 96];
        for (int o = 16; o; o >>= 1) v += __shfl_down_sync(~0u, v, o);
        if (lane == 0) {
            if (r & 1) g_nrmp[h][i][n * KK + k0 + k] = v;
            else       g_dotp[h][i][n * KK + k0 + k] = v;
        }
    }
}

// ================= k3: per-(i,n) NCE loss; last block combines everything ============
__global__ void __launch_bounds__(256) k3(const float* __restrict__ att,
                                          float* __restrict__ out)
{
    int i = blockIdx.x >> 6, n = blockIdx.x & 63;
    int tid = threadIdx.x, wid = tid >> 5, lane = tid & 31;

    float4 S0 = make_float4(0.f,0.f,0.f,0.f), S1 = S0, E0 = S0, E1 = S0;
#pragma unroll
    for (int p = 0; p < 4; ++p) {
        float4 a = g_Sp[p][i][n * C4 + tid];
        float4 b = g_Sp[p][i][n * C4 + 256 + tid];
        S0.x += a.x; S0.y += a.y; S0.z += a.z; S0.w += a.w;
        S1.x += b.x; S1.y += b.y; S1.z += b.z; S1.w += b.w;
    }
#pragma unroll
    for (int p = 0; p < 10; ++p) {
        float4 a = g_SEp[p][1 - i][n * C4 + tid];
        float4 b = g_SEp[p][1 - i][n * C4 + 256 + tid];
        E0.x += a.x; E0.y += a.y; E0.z += a.z; E0.w += a.w;
        E1.x += b.x; E1.y += b.y; E1.z += b.z; E1.w += b.w;
    }
    float qss  = S0.x*S0.x+S0.y*S0.y+S0.z*S0.z+S0.w*S0.w + S1.x*S1.x+S1.y*S1.y+S1.z*S1.z+S1.w*S1.w;
    float sess = E0.x*E0.x+E0.y*E0.y+E0.z*E0.z+E0.w*E0.w + E1.x*E1.x+E1.y*E1.y+E1.z*E1.z+E1.w*E1.w;
    float dse  = S0.x*E0.x+S0.y*E0.y+S0.z*E0.z+S0.w*E0.w + S1.x*E1.x+S1.y*E1.y+S1.z*E1.z+S1.w*E1.w;

    __shared__ float sm[8][4];
    __shared__ float bc[2];
    for (int o = 16; o; o >>= 1) {
        qss  += __shfl_down_sync(~0u, qss,  o);
        sess += __shfl_down_sync(~0u, sess, o);
        dse  += __shfl_down_sync(~0u, dse,  o);
    }
    if (lane == 0) { sm[wid][0] = qss; sm[wid][1] = sess; sm[wid][2] = dse; }
    __syncthreads();
    if (tid == 0) {
        float Q = 0.f, S = 0.f, D = 0.f;
        for (int w = 0; w < 8; ++w) { Q += sm[w][0]; S += sm[w][1]; D += sm[w][2]; }
        float rq = rsqrtf(Q);
        bc[0] = rq;
        bc[1] = D * rq * rsqrtf(S) * (1.f / T_NCE);    // logit0
    }
    __syncthreads();
    float rq = bc[0], logit0 = bc[1];

    float logit = -1e30f;
    if (tid == 0) logit = logit0;
    else if (tid <= 150) {
        int k = tid - 1;
        float dd = g_dotp[0][i][n * KK + k] + g_dotp[1][i][n * KK + k];
        float nn = g_nrmp[0][i][n * KK + k] + g_nrmp[1][i][n * KK + k];
        logit = att[n * 300 + i * 150 + k] * dd * rq * rsqrtf(nn) * (1.f / T_NCE);
    }
    // block max
    float mx = logit;
    for (int o = 16; o; o >>= 1) mx = fmaxf(mx, __shfl_xor_sync(~0u, mx, o));
    if (lane == 0) sm[wid][0] = mx;
    __syncthreads();
    if (tid == 0) {
        float M = -1e30f;
        for (int w = 0; w < 8; ++w) M = fmaxf(M, sm[w][0]);
        bc[0] = M;
    }
    __syncthreads();
    float M = bc[0];
    float ex = (tid <= 150) ? expf(logit - M) : 0.f;
    for (int o = 16; o; o >>= 1) ex += __shfl_down_sync(~0u, ex, o);
    if (lane == 0) sm[wid][1] = ex;
    __syncthreads();
    if (tid == 0) {
        float SE = 0.f;
        for (int w = 0; w < 8; ++w) SE += sm[w][1];
        g_nce[i * 64 + n] = logf(SE) + M - logit0;     // -log_softmax[0]
    }

    // ---- last-block final combine ----
    __shared__ unsigned last;
    __threadfence();
    __syncthreads();
    if (tid == 0) last = (atomicAdd(&g_ctr, 1u) == (unsigned)(gridDim.x - 1)) ? 1u : 0u;
    __syncthreads();
    if (!last) return;
    __threadfence();   // acquire: see all blocks' g_nce writes

    float sn2 = 0.f, sw = 0.f, ss = 0.f, sr = 0.f;
    for (int e = tid; e < 2 * BB; e += 256) sn2 += g_nce[e];
    for (int e = tid; e < TL; e += 256) { sw += g_actw[e]; ss += g_acts[e]; }
    if (tid < 16) sr = g_rel[tid >> 1][tid & 1];
    for (int o = 16; o; o >>= 1) {
        sn2 += __shfl_down_sync(~0u, sn2, o);
        sw  += __shfl_down_sync(~0u, sw,  o);
        ss  += __shfl_down_sync(~0u, ss,  o);
        sr  += __shfl_down_sync(~0u, sr,  o);
    }
    if (lane == 0) { sm[wid][0]=sn2; sm[wid][1]=sw; sm[wid][2]=ss; sm[wid][3]=sr; }
    __syncthreads();
    if (tid == 0) {
        float SN=0.f, SW=0.f, SS=0.f, SR=0.f;
        for (int w = 0; w < 8; ++w) { SN+=sm[w][0]; SW+=sm[w][1]; SS+=sm[w][2]; SR+=sm[w][3]; }
        float cls   = -g_cls * (1.f / (BB * NCC));
        float rel   = SR * (1.f / (2 * BB * TL));
        float act   = SW + 0.1f * SS * (1.f / BB);     // E_THETA=0.1, E_ALPHA=1
        float snico = SN * (1.f / BB);
        out[0] = cls + 0.01f * snico + act + 0.1f * rel;
        out[1] = cls; out[2] = snico; out[3] = act; out[4] = rel;
        g_ctr = 0;                                     // reset for next graph replay
    }
}

extern "C" void kernel_launch(void* const* d_in, const int* in_sizes, int n_in,
                              void* d_out, int out_size) {
    const float* video = (const float*)d_in[0];
    const float* label = (const float*)d_in[1];
    const float* HA    = (const float*)d_in[2];
    const float* EA    = (const float*)d_in[3];
    const float* HB    = (const float*)d_in[4];
    const float* EB    = (const float*)d_in[5];
    const float* rs    = (const float*)d_in[6];
    const float* rd    = (const float*)d_in[7];
    const float* a0    = (const float*)d_in[8];
    const float* a2    = (const float*)d_in[9];
    const float* att   = (const float*)d_in[10];
    float* out = (float*)d_out;

    k1<<<1033 + 188, 256>>>(HA, HB, video, label, rs, rd, a0, a2);
    k2<<<2560, 256>>>(EA, EB);
    k3<<<128, 256>>>(att, out);
    (void)in_sizes; (void)n_in; (void)out_size;
}